// round 6
// baseline (speedup 1.0000x reference)
#include <cuda_runtime.h>

#define N_NODES 100000
#define MAX_E   1600000
#define FDIM    64
#define N4      (N_NODES * (FDIM / 4))       // float4 elems per feature table
#define NCHUNK  ((N_NODES + 255) / 256)      // 391 scan chunks

// ---- scratch (device globals referenced directly by kernels) ----
__device__ int    d_mode;                    // 1 = edge_index is int64, 0 = int32
__device__ int    d_deg[N_NODES];            // in-degree (real edges only)
__device__ int    d_rowstart[N_NODES];       // CSR row offsets (exclusive scan)
__device__ int    d_cursor[N_NODES];         // scatter cursors
__device__ float  d_dinv[N_NODES];           // (1+deg)^{-1/2}
__device__ int    d_srcA[MAX_E];
__device__ int    d_dstA[MAX_E];
__device__ int    d_srcSorted[MAX_E];        // src indices grouped by dst
__device__ int    d_chunksum[512];           // per-chunk scan sums
__device__ float4 d_g[N_NODES * (FDIM / 4)]; // raw linear output (A @ W)
__device__ float4 d_h[N_NODES * (FDIM / 4)]; // hidden activations

// zero degrees; block 0 also detects edge_index dtype (int64 LE values < 2^32
// have all odd int32 words zero; int32 node ids make that vanishingly unlikely)
__global__ void k_init(const int* __restrict__ ei32) {
    int i = blockIdx.x * blockDim.x + threadIdx.x;
    if (i < N_NODES) d_deg[i] = 0;
    if (blockIdx.x == 0 && threadIdx.x < 32) {
        int nz = 0;
        for (int k = threadIdx.x; k < 512; k += 32)
            if (ei32[2 * k + 1] != 0) nz = 1;
        nz = __any_sync(0xffffffffu, nz);
        if (threadIdx.x == 0) d_mode = nz ? 0 : 1;
    }
}

// decode edges (either dtype) -> int32 src/dst, count in-degree
__global__ void k_edge(const int* __restrict__ ei, int E) {
    int e = blockIdx.x * blockDim.x + threadIdx.x;
    if (e >= E) return;
    int s, d;
    if (d_mode) {                 // int64: take low word of element e / E+e
        s = ei[2 * e];
        d = ei[2 * (E + e)];
    } else {                      // int32
        s = ei[e];
        d = ei[E + e];
    }
    if ((unsigned)s >= (unsigned)N_NODES) s = 0;   // safety clamp
    if ((unsigned)d >= (unsigned)N_NODES) d = 0;
    d_srcA[e] = s;
    d_dstA[e] = d;
    atomicAdd(&d_deg[d], 1);
}

// phase 1: per-256-chunk exclusive scan of deg (warp-shuffle), chunk totals out
__global__ void k_scan1() {
    __shared__ int wsum[8];
    int i = threadIdx.x;
    int gi = blockIdx.x * 256 + i;
    int v = (gi < N_NODES) ? d_deg[gi] : 0;
    int lane = i & 31, w = i >> 5;
    int x = v;
    #pragma unroll
    for (int off = 1; off < 32; off <<= 1) {
        int t = __shfl_up_sync(0xffffffffu, x, off);
        if (lane >= off) x += t;
    }
    if (lane == 31) wsum[w] = x;
    __syncthreads();
    if (w == 0) {
        int s = (lane < 8) ? wsum[lane] : 0;
        #pragma unroll
        for (int off = 1; off < 8; off <<= 1) {
            int t = __shfl_up_sync(0xffffffffu, s, off);
            if (lane >= off) s += t;
        }
        if (lane < 8) wsum[lane] = s;
    }
    __syncthreads();
    int excl = x - v + (w > 0 ? wsum[w - 1] : 0);
    if (gi < N_NODES) d_rowstart[gi] = excl;
    if (i == 255) d_chunksum[blockIdx.x] = wsum[7];
}

// phase 2: single block exclusive scan of chunk sums (NCHUNK <= 512)
__global__ void k_scan2() {
    __shared__ int sm[512];
    int i = threadIdx.x;
    int v = (i < NCHUNK) ? d_chunksum[i] : 0;
    sm[i] = v;
    __syncthreads();
    #pragma unroll
    for (int off = 1; off < 512; off <<= 1) {
        int t = (i >= off) ? sm[i - off] : 0;
        __syncthreads();
        sm[i] += t;
        __syncthreads();
    }
    if (i < NCHUNK) d_chunksum[i] = sm[i] - v;      // exclusive
}

// phase 3: finalize rowstart, init cursors, compute dinv = rsqrt(1+deg)
__global__ void k_scan3() {
    int gi = blockIdx.x * blockDim.x + threadIdx.x;
    if (gi >= N_NODES) return;
    int rs = d_rowstart[gi] + d_chunksum[gi >> 8];
    d_rowstart[gi] = rs;
    d_cursor[gi] = rs;
    d_dinv[gi] = rsqrtf(1.0f + (float)d_deg[gi]);
}

// bucket src indices by dst (order within bucket irrelevant for a sum)
__global__ void k_scatter(int E) {
    int e = blockIdx.x * blockDim.x + threadIdx.x;
    if (e >= E) return;
    int d = d_dstA[e];
    int pos = atomicAdd(&d_cursor[d], 1);
    d_srcSorted[pos] = d_srcA[e];
}

// g[row] = A[row] @ W (raw, no scaling -> independent of CSR build)
// block: 256 threads, 64x64 output tile, 4x4 register tile per thread
__global__ __launch_bounds__(256) void k_gemm(
    const float* __restrict__ A_ext, const float* __restrict__ W,
    int M, int src_sel) {
    __shared__ float As[64][68];   // k-major: As[k][row]
    __shared__ float Ws[64][68];   // k-major: Ws[k][col]
    const int t = threadIdx.x;
    const int block_row = blockIdx.x * 64;
    const float4* A4 = src_sel ? (const float4*)d_h : (const float4*)A_ext;

    #pragma unroll
    for (int r = 0; r < 4; r++) {
        int p = t + r * 256;          // float4 index 0..1023
        int k = p >> 4;
        int c4 = p & 15;
        float4 w = ((const float4*)W)[p];
        *(float4*)&Ws[k][c4 * 4] = w;
    }
    #pragma unroll
    for (int r = 0; r < 4; r++) {
        int p = t + r * 256;
        int row = p >> 4;
        int k4 = p & 15;
        int grow = block_row + row;
        float4 a = (grow < M) ? A4[grow * 16 + k4]
                              : make_float4(0.f, 0.f, 0.f, 0.f);
        As[k4 * 4 + 0][row] = a.x;
        As[k4 * 4 + 1][row] = a.y;
        As[k4 * 4 + 2][row] = a.z;
        As[k4 * 4 + 3][row] = a.w;
    }
    __syncthreads();

    const int tx = t & 15;   // col group
    const int ty = t >> 4;   // row group
    float acc[4][4] = {};
    #pragma unroll
    for (int k = 0; k < 64; k++) {
        float4 av = *(const float4*)&As[k][ty * 4];
        float4 bv = *(const float4*)&Ws[k][tx * 4];
        acc[0][0] += av.x * bv.x; acc[0][1] += av.x * bv.y; acc[0][2] += av.x * bv.z; acc[0][3] += av.x * bv.w;
        acc[1][0] += av.y * bv.x; acc[1][1] += av.y * bv.y; acc[1][2] += av.y * bv.z; acc[1][3] += av.y * bv.w;
        acc[2][0] += av.z * bv.x; acc[2][1] += av.z * bv.y; acc[2][2] += av.z * bv.z; acc[2][3] += av.z * bv.w;
        acc[3][0] += av.w * bv.x; acc[3][1] += av.w * bv.y; acc[3][2] += av.w * bv.z; acc[3][3] += av.w * bv.w;
    }
    #pragma unroll
    for (int i = 0; i < 4; i++) {
        int grow = block_row + ty * 4 + i;
        if (grow < M) {
            d_g[grow * 16 + tx] = make_float4(acc[i][0], acc[i][1],
                                              acc[i][2], acc[i][3]);
        }
    }
}

// fused aggregation + epilogue: 16 threads per dst node,
// out[d] = [relu]( dinv[d] * (sum_e dinv[src_e]*g[src_e] + dinv[d]*g[d]) + b )
// dst_sel: 1 -> write d_h with relu ; 0 -> write external out
__global__ void k_gat(const float4* __restrict__ b, float4* __restrict__ out_ext,
                      int dst_sel) {
    int t = blockIdx.x * blockDim.x + threadIdx.x;
    int node = t >> 4;
    if (node >= N_NODES) return;
    int c = t & 15;

    float dv = d_dinv[node];
    float4 gs = d_g[node * 16 + c];        // self loop (weight dinv[d])
    float4 acc = make_float4(dv * gs.x, dv * gs.y, dv * gs.z, dv * gs.w);
    int start = d_rowstart[node];
    int cnt = d_deg[node];

    int j = 0;
    for (; j + 4 <= cnt; j += 4) {         // 4-wide: batch loads for MLP
        int s0 = d_srcSorted[start + j + 0];
        int s1 = d_srcSorted[start + j + 1];
        int s2 = d_srcSorted[start + j + 2];
        int s3 = d_srcSorted[start + j + 3];
        float w0 = d_dinv[s0], w1 = d_dinv[s1], w2 = d_dinv[s2], w3 = d_dinv[s3];
        float4 v0 = d_g[s0 * 16 + c];
        float4 v1 = d_g[s1 * 16 + c];
        float4 v2 = d_g[s2 * 16 + c];
        float4 v3 = d_g[s3 * 16 + c];
        acc.x += w0 * v0.x + w1 * v1.x + w2 * v2.x + w3 * v3.x;
        acc.y += w0 * v0.y + w1 * v1.y + w2 * v2.y + w3 * v3.y;
        acc.z += w0 * v0.z + w1 * v1.z + w2 * v2.z + w3 * v3.z;
        acc.w += w0 * v0.w + w1 * v1.w + w2 * v2.w + w3 * v3.w;
    }
    for (; j < cnt; j++) {
        int si = d_srcSorted[start + j];
        float wv = d_dinv[si];
        float4 v = d_g[si * 16 + c];
        acc.x += wv * v.x; acc.y += wv * v.y;
        acc.z += wv * v.z; acc.w += wv * v.w;
    }

    float4 bv = b[c];
    float4 o;
    o.x = fmaf(dv, acc.x, bv.x);
    o.y = fmaf(dv, acc.y, bv.y);
    o.z = fmaf(dv, acc.z, bv.z);
    o.w = fmaf(dv, acc.w, bv.w);
    if (dst_sel) {
        o.x = fmaxf(o.x, 0.f); o.y = fmaxf(o.y, 0.f);
        o.z = fmaxf(o.z, 0.f); o.w = fmaxf(o.w, 0.f);
        d_h[node * 16 + c] = o;
    } else {
        out_ext[node * 16 + c] = o;
    }
}

extern "C" void kernel_launch(void* const* d_in, const int* in_sizes, int n_in,
                              void* d_out, int out_size) {
    const float* x  = (const float*)d_in[0];
    const int*   ei = (const int*)d_in[1];     // int32 view; int64 handled via d_mode
    const float* W1 = (const float*)d_in[2];
    const float* b1 = (const float*)d_in[3];
    const float* W2 = (const float*)d_in[4];
    const float* b2 = (const float*)d_in[5];
    const int E = in_sizes[1] / 2;             // elements of edge_index / 2

    const int TPB = 256;
    const int gridN    = (N_NODES + TPB - 1) / TPB;      // 391
    const int gridE    = (E + TPB - 1) / TPB;
    const int gridGat  = (N_NODES * 16 + TPB - 1) / TPB; // 6250
    const int gridGemm = (N_NODES + 63) / 64;

    // one-time resources (host objects only; no device memory)
    static cudaStream_t s2 = nullptr;
    static cudaEvent_t evFork = nullptr, evJoin = nullptr;
    if (!s2) {
        cudaStreamCreateWithFlags(&s2, cudaStreamNonBlocking);
        cudaEventCreateWithFlags(&evFork, cudaEventDisableTiming);
        cudaEventCreateWithFlags(&evJoin, cudaEventDisableTiming);
    }
    bool overlap = (s2 && evFork && evJoin);

    if (overlap) {
        // fork: GEMM1 (only needs x, W1) runs concurrently with the CSR build
        cudaEventRecord(evFork, 0);
        cudaStreamWaitEvent(s2, evFork, 0);
        k_gemm<<<gridGemm, TPB, 0, s2>>>(x, W1, N_NODES, 0);
        cudaEventRecord(evJoin, s2);
    }

    // ---- CSR build (per run) ----
    k_init<<<gridN, TPB>>>(ei);
    k_edge<<<gridE, TPB>>>(ei, E);
    k_scan1<<<NCHUNK, 256>>>();
    k_scan2<<<1, 512>>>();
    k_scan3<<<gridN, TPB>>>();
    k_scatter<<<gridE, TPB>>>(E);

    if (overlap) {
        cudaStreamWaitEvent(0, evJoin, 0);     // join before gat1 reads d_g
    } else {
        k_gemm<<<gridGemm, TPB>>>(x, W1, N_NODES, 0);
    }

    // ---- layer 1 ----
    k_gat<<<gridGat, TPB>>>((const float4*)b1, nullptr, 1);

    // ---- layer 2 ----
    k_gemm<<<gridGemm, TPB>>>(nullptr, W2, N_NODES, 1);
    k_gat<<<gridGat, TPB>>>((const float4*)b2, (float4*)d_out, 0);
}

// round 7
// speedup vs baseline: 1.0456x; 1.0456x over previous
#include <cuda_runtime.h>

#define N_NODES 100000
#define MAX_E   1600000
#define FDIM    64
#define N4      (N_NODES * (FDIM / 4))       // float4 elems per feature table
#define NCHUNK  ((N_NODES + 255) / 256)      // 391 scan chunks

// ---- scratch (device globals referenced directly by kernels) ----
__device__ int    d_mode;                    // 1 = edge_index is int64, 0 = int32
__device__ int    d_deg[N_NODES];            // in-degree (real edges only)
__device__ int    d_rowstart[N_NODES];       // CSR row offsets (exclusive scan)
__device__ int    d_cursor[N_NODES];         // scatter cursors
__device__ float  d_dinv[N_NODES];           // (1+deg)^{-1/2}
__device__ int    d_srcA[MAX_E];
__device__ int    d_dstA[MAX_E];
__device__ int    d_srcSorted[MAX_E];        // src indices grouped by dst
__device__ int    d_chunksum[512];           // per-chunk scan sums
__device__ float4 d_g[N_NODES * (FDIM / 4)]; // dinv-scaled linear output
__device__ float4 d_h[N_NODES * (FDIM / 4)]; // hidden activations

// zero degrees; block 0 also detects edge_index dtype (int64 LE values < 2^32
// have all odd int32 words zero; int32 node ids make that vanishingly unlikely)
__global__ void k_init(const int* __restrict__ ei32) {
    int i = blockIdx.x * blockDim.x + threadIdx.x;
    if (i < N_NODES) d_deg[i] = 0;
    if (blockIdx.x == 0 && threadIdx.x < 32) {
        int nz = 0;
        for (int k = threadIdx.x; k < 512; k += 32)
            if (ei32[2 * k + 1] != 0) nz = 1;
        nz = __any_sync(0xffffffffu, nz);
        if (threadIdx.x == 0) d_mode = nz ? 0 : 1;
    }
}

// decode edges (either dtype) -> int32 src/dst, count in-degree
__global__ void k_edge(const int* __restrict__ ei, int E) {
    int e = blockIdx.x * blockDim.x + threadIdx.x;
    if (e >= E) return;
    int s, d;
    if (d_mode) {                 // int64: take low word of element e / E+e
        s = ei[2 * e];
        d = ei[2 * (E + e)];
    } else {                      // int32
        s = ei[e];
        d = ei[E + e];
    }
    if ((unsigned)s >= (unsigned)N_NODES) s = 0;   // safety clamp
    if ((unsigned)d >= (unsigned)N_NODES) d = 0;
    d_srcA[e] = s;
    d_dstA[e] = d;
    atomicAdd(&d_deg[d], 1);
}

// phase 1: per-256-chunk exclusive scan of deg (warp-shuffle), chunk totals out
__global__ void k_scan1() {
    __shared__ int wsum[8];
    int i = threadIdx.x;
    int gi = blockIdx.x * 256 + i;
    int v = (gi < N_NODES) ? d_deg[gi] : 0;
    int lane = i & 31, w = i >> 5;
    int x = v;
    #pragma unroll
    for (int off = 1; off < 32; off <<= 1) {
        int t = __shfl_up_sync(0xffffffffu, x, off);
        if (lane >= off) x += t;
    }
    if (lane == 31) wsum[w] = x;
    __syncthreads();
    if (w == 0) {
        int s = (lane < 8) ? wsum[lane] : 0;
        #pragma unroll
        for (int off = 1; off < 8; off <<= 1) {
            int t = __shfl_up_sync(0xffffffffu, s, off);
            if (lane >= off) s += t;
        }
        if (lane < 8) wsum[lane] = s;
    }
    __syncthreads();
    int excl = x - v + (w > 0 ? wsum[w - 1] : 0);
    if (gi < N_NODES) d_rowstart[gi] = excl;
    if (i == 255) d_chunksum[blockIdx.x] = wsum[7];
}

// phase 2: single block exclusive scan of chunk sums (NCHUNK <= 512)
__global__ void k_scan2() {
    __shared__ int sm[512];
    int i = threadIdx.x;
    int v = (i < NCHUNK) ? d_chunksum[i] : 0;
    sm[i] = v;
    __syncthreads();
    #pragma unroll
    for (int off = 1; off < 512; off <<= 1) {
        int t = (i >= off) ? sm[i - off] : 0;
        __syncthreads();
        sm[i] += t;
        __syncthreads();
    }
    if (i < NCHUNK) d_chunksum[i] = sm[i] - v;      // exclusive
}

// phase 3: finalize rowstart, init cursors, compute dinv = rsqrt(1+deg)
__global__ void k_scan3() {
    int gi = blockIdx.x * blockDim.x + threadIdx.x;
    if (gi >= N_NODES) return;
    int rs = d_rowstart[gi] + d_chunksum[gi >> 8];
    d_rowstart[gi] = rs;
    d_cursor[gi] = rs;
    d_dinv[gi] = rsqrtf(1.0f + (float)d_deg[gi]);
}

// bucket src indices by dst (order within bucket irrelevant for a sum)
__global__ void k_scatter(int E) {
    int e = blockIdx.x * blockDim.x + threadIdx.x;
    if (e >= E) return;
    int d = d_dstA[e];
    int pos = atomicAdd(&d_cursor[d], 1);
    d_srcSorted[pos] = d_srcA[e];
}

// g[row] = (A[row] @ W) * dinv[row];  M x 64 @ 64 x 64
// block: 256 threads, 64x64 output tile, 4x4 register tile per thread
__global__ __launch_bounds__(256) void k_gemm(
    const float* __restrict__ A_ext, const float* __restrict__ W,
    int M, int src_sel) {
    __shared__ float As[64][68];   // k-major: As[k][row]
    __shared__ float Ws[64][68];   // k-major: Ws[k][col]
    const int t = threadIdx.x;
    const int block_row = blockIdx.x * 64;
    const float4* A4 = src_sel ? (const float4*)d_h : (const float4*)A_ext;

    #pragma unroll
    for (int r = 0; r < 4; r++) {
        int p = t + r * 256;          // float4 index 0..1023
        int k = p >> 4;
        int c4 = p & 15;
        float4 w = ((const float4*)W)[p];
        *(float4*)&Ws[k][c4 * 4] = w;
    }
    #pragma unroll
    for (int r = 0; r < 4; r++) {
        int p = t + r * 256;
        int row = p >> 4;
        int k4 = p & 15;
        int grow = block_row + row;
        float4 a = (grow < M) ? A4[grow * 16 + k4]
                              : make_float4(0.f, 0.f, 0.f, 0.f);
        As[k4 * 4 + 0][row] = a.x;
        As[k4 * 4 + 1][row] = a.y;
        As[k4 * 4 + 2][row] = a.z;
        As[k4 * 4 + 3][row] = a.w;
    }
    __syncthreads();

    const int tx = t & 15;   // col group
    const int ty = t >> 4;   // row group
    float acc[4][4] = {};
    #pragma unroll
    for (int k = 0; k < 64; k++) {
        float4 av = *(const float4*)&As[k][ty * 4];
        float4 bv = *(const float4*)&Ws[k][tx * 4];
        acc[0][0] += av.x * bv.x; acc[0][1] += av.x * bv.y; acc[0][2] += av.x * bv.z; acc[0][3] += av.x * bv.w;
        acc[1][0] += av.y * bv.x; acc[1][1] += av.y * bv.y; acc[1][2] += av.y * bv.z; acc[1][3] += av.y * bv.w;
        acc[2][0] += av.z * bv.x; acc[2][1] += av.z * bv.y; acc[2][2] += av.z * bv.z; acc[2][3] += av.z * bv.w;
        acc[3][0] += av.w * bv.x; acc[3][1] += av.w * bv.y; acc[3][2] += av.w * bv.z; acc[3][3] += av.w * bv.w;
    }
    #pragma unroll
    for (int i = 0; i < 4; i++) {
        int grow = block_row + ty * 4 + i;
        if (grow < M) {
            float sc = d_dinv[grow];
            d_g[grow * 16 + tx] = make_float4(acc[i][0] * sc, acc[i][1] * sc,
                                              acc[i][2] * sc, acc[i][3] * sc);
        }
    }
}

// fused aggregation + epilogue: 16 threads per dst node, gather-reduce,
// out[d] = [relu]( dinv[d] * (sum_{e: dst=d} g[src_e] + g[d]) + b )
// dst_sel: 1 -> write d_h with relu ; 0 -> write external out
__global__ void k_gat(const float4* __restrict__ b, float4* __restrict__ out_ext,
                      int dst_sel) {
    const float4* __restrict__ g   = d_g;
    const int*    __restrict__ srt = d_srcSorted;

    int t = blockIdx.x * blockDim.x + threadIdx.x;
    int node = t >> 4;
    if (node >= N_NODES) return;
    int c = t & 15;

    float4 acc = g[node * 16 + c];         // self loop (already dinv-scaled)
    int start = d_rowstart[node];
    int cnt = d_deg[node];

    int j = 0;
    for (; j + 4 <= cnt; j += 4) {         // 4-wide: batch loads for MLP
        int s0 = srt[start + j + 0];
        int s1 = srt[start + j + 1];
        int s2 = srt[start + j + 2];
        int s3 = srt[start + j + 3];
        float4 v0 = g[s0 * 16 + c];
        float4 v1 = g[s1 * 16 + c];
        float4 v2 = g[s2 * 16 + c];
        float4 v3 = g[s3 * 16 + c];
        acc.x += v0.x + v1.x + v2.x + v3.x;
        acc.y += v0.y + v1.y + v2.y + v3.y;
        acc.z += v0.z + v1.z + v2.z + v3.z;
        acc.w += v0.w + v1.w + v2.w + v3.w;
    }
    for (; j < cnt; j++) {
        int si = srt[start + j];
        float4 v = g[si * 16 + c];
        acc.x += v.x; acc.y += v.y; acc.z += v.z; acc.w += v.w;
    }

    float dv = d_dinv[node];
    float4 bv = b[c];
    float4 o;
    o.x = fmaf(dv, acc.x, bv.x);
    o.y = fmaf(dv, acc.y, bv.y);
    o.z = fmaf(dv, acc.z, bv.z);
    o.w = fmaf(dv, acc.w, bv.w);
    if (dst_sel) {
        o.x = fmaxf(o.x, 0.f); o.y = fmaxf(o.y, 0.f);
        o.z = fmaxf(o.z, 0.f); o.w = fmaxf(o.w, 0.f);
        d_h[node * 16 + c] = o;
    } else {
        out_ext[node * 16 + c] = o;
    }
}

extern "C" void kernel_launch(void* const* d_in, const int* in_sizes, int n_in,
                              void* d_out, int out_size) {
    const float* x  = (const float*)d_in[0];
    const int*   ei = (const int*)d_in[1];     // int32 view; int64 handled via d_mode
    const float* W1 = (const float*)d_in[2];
    const float* b1 = (const float*)d_in[3];
    const float* W2 = (const float*)d_in[4];
    const float* b2 = (const float*)d_in[5];
    const int E = in_sizes[1] / 2;             // elements of edge_index / 2

    const int TPB = 256;
    const int gridN    = (N_NODES + TPB - 1) / TPB;      // 391
    const int gridE    = (E + TPB - 1) / TPB;
    const int gridGat  = (N_NODES * 16 + TPB - 1) / TPB; // 6250
    const int gridGemm = (N_NODES + 63) / 64;

    // ---- CSR build (per run) ----
    k_init<<<gridN, TPB>>>(ei);
    k_edge<<<gridE, TPB>>>(ei, E);
    k_scan1<<<NCHUNK, 256>>>();
    k_scan2<<<1, 512>>>();
    k_scan3<<<gridN, TPB>>>();
    k_scatter<<<gridE, TPB>>>(E);

    // ---- layer 1 ----
    k_gemm<<<gridGemm, TPB>>>(x, W1, N_NODES, 0);
    k_gat<<<gridGat, TPB>>>((const float4*)b1, nullptr, 1);

    // ---- layer 2 ----
    k_gemm<<<gridGemm, TPB>>>(nullptr, W2, N_NODES, 1);
    k_gat<<<gridGat, TPB>>>((const float4*)b2, (float4*)d_out, 0);
}

// round 8
// speedup vs baseline: 1.0857x; 1.0383x over previous
#include <cuda_runtime.h>
#include <cuda_fp16.h>

#define N_NODES 100000
#define MAX_E   1600000
#define FDIM    64
#define N4      (N_NODES * (FDIM / 4))       // float4 elems per feature table
#define NCHUNK  ((N_NODES + 255) / 256)      // 391 scan chunks

// ---- scratch (device globals referenced directly by kernels) ----
__device__ int    d_mode;                    // 1 = edge_index is int64, 0 = int32
__device__ int    d_deg[N_NODES];            // in-degree (real edges only)
__device__ int    d_rowstart[N_NODES];       // CSR row offsets (exclusive scan)
__device__ int    d_cursor[N_NODES];         // scatter cursors
__device__ float  d_dinv[N_NODES];           // (1+deg)^{-1/2}
__device__ int    d_srcA[MAX_E];
__device__ int    d_dstA[MAX_E];
__device__ int    d_srcSorted[MAX_E];        // src indices grouped by dst
__device__ int    d_chunksum[512];           // per-chunk scan sums
__device__ uint4  d_gh[N_NODES * 8];         // dinv-scaled linear output, fp16 (128B/row)
__device__ float4 d_h[N_NODES * (FDIM / 4)]; // hidden activations (fp32)

// zero degrees; block 0 also detects edge_index dtype (int64 LE values < 2^32
// have all odd int32 words zero; int32 node ids make that vanishingly unlikely)
__global__ void k_init(const int* __restrict__ ei32) {
    int i = blockIdx.x * blockDim.x + threadIdx.x;
    if (i < N_NODES) d_deg[i] = 0;
    if (blockIdx.x == 0 && threadIdx.x < 32) {
        int nz = 0;
        for (int k = threadIdx.x; k < 512; k += 32)
            if (ei32[2 * k + 1] != 0) nz = 1;
        nz = __any_sync(0xffffffffu, nz);
        if (threadIdx.x == 0) d_mode = nz ? 0 : 1;
    }
}

// decode edges (either dtype) -> int32 src/dst, count in-degree
__global__ void k_edge(const int* __restrict__ ei, int E) {
    int e = blockIdx.x * blockDim.x + threadIdx.x;
    if (e >= E) return;
    int s, d;
    if (d_mode) {                 // int64: take low word of element e / E+e
        s = ei[2 * e];
        d = ei[2 * (E + e)];
    } else {                      // int32
        s = ei[e];
        d = ei[E + e];
    }
    if ((unsigned)s >= (unsigned)N_NODES) s = 0;   // safety clamp
    if ((unsigned)d >= (unsigned)N_NODES) d = 0;
    d_srcA[e] = s;
    d_dstA[e] = d;
    atomicAdd(&d_deg[d], 1);
}

// phase 1: per-256-chunk exclusive scan of deg (warp-shuffle), chunk totals out
__global__ void k_scan1() {
    __shared__ int wsum[8];
    int i = threadIdx.x;
    int gi = blockIdx.x * 256 + i;
    int v = (gi < N_NODES) ? d_deg[gi] : 0;
    int lane = i & 31, w = i >> 5;
    int x = v;
    #pragma unroll
    for (int off = 1; off < 32; off <<= 1) {
        int t = __shfl_up_sync(0xffffffffu, x, off);
        if (lane >= off) x += t;
    }
    if (lane == 31) wsum[w] = x;
    __syncthreads();
    if (w == 0) {
        int s = (lane < 8) ? wsum[lane] : 0;
        #pragma unroll
        for (int off = 1; off < 8; off <<= 1) {
            int t = __shfl_up_sync(0xffffffffu, s, off);
            if (lane >= off) s += t;
        }
        if (lane < 8) wsum[lane] = s;
    }
    __syncthreads();
    int excl = x - v + (w > 0 ? wsum[w - 1] : 0);
    if (gi < N_NODES) d_rowstart[gi] = excl;
    if (i == 255) d_chunksum[blockIdx.x] = wsum[7];
}

// phase 2: single block exclusive scan of chunk sums (NCHUNK <= 512)
__global__ void k_scan2() {
    __shared__ int sm[512];
    int i = threadIdx.x;
    int v = (i < NCHUNK) ? d_chunksum[i] : 0;
    sm[i] = v;
    __syncthreads();
    #pragma unroll
    for (int off = 1; off < 512; off <<= 1) {
        int t = (i >= off) ? sm[i - off] : 0;
        __syncthreads();
        sm[i] += t;
        __syncthreads();
    }
    if (i < NCHUNK) d_chunksum[i] = sm[i] - v;      // exclusive
}

// phase 3: finalize rowstart, init cursors, compute dinv = rsqrt(1+deg)
__global__ void k_scan3() {
    int gi = blockIdx.x * blockDim.x + threadIdx.x;
    if (gi >= N_NODES) return;
    int rs = d_rowstart[gi] + d_chunksum[gi >> 8];
    d_rowstart[gi] = rs;
    d_cursor[gi] = rs;
    d_dinv[gi] = rsqrtf(1.0f + (float)d_deg[gi]);
}

// bucket src indices by dst (order within bucket irrelevant for a sum)
__global__ void k_scatter(int E) {
    int e = blockIdx.x * blockDim.x + threadIdx.x;
    if (e >= E) return;
    int d = d_dstA[e];
    int pos = atomicAdd(&d_cursor[d], 1);
    d_srcSorted[pos] = d_srcA[e];
}

// g[row] = fp16( (A[row] @ W) * dinv[row] );  M x 64 @ 64 x 64
// block: 256 threads, 64x64 output tile, 4x4 register tile per thread
__global__ __launch_bounds__(256) void k_gemm(
    const float* __restrict__ A_ext, const float* __restrict__ W,
    int M, int src_sel) {
    __shared__ float As[64][68];   // k-major: As[k][row]
    __shared__ float Ws[64][68];   // k-major: Ws[k][col]
    const int t = threadIdx.x;
    const int block_row = blockIdx.x * 64;
    const float4* A4 = src_sel ? (const float4*)d_h : (const float4*)A_ext;

    #pragma unroll
    for (int r = 0; r < 4; r++) {
        int p = t + r * 256;          // float4 index 0..1023
        int k = p >> 4;
        int c4 = p & 15;
        float4 w = ((const float4*)W)[p];
        *(float4*)&Ws[k][c4 * 4] = w;
    }
    #pragma unroll
    for (int r = 0; r < 4; r++) {
        int p = t + r * 256;
        int row = p >> 4;
        int k4 = p & 15;
        int grow = block_row + row;
        float4 a = (grow < M) ? A4[grow * 16 + k4]
                              : make_float4(0.f, 0.f, 0.f, 0.f);
        As[k4 * 4 + 0][row] = a.x;
        As[k4 * 4 + 1][row] = a.y;
        As[k4 * 4 + 2][row] = a.z;
        As[k4 * 4 + 3][row] = a.w;
    }
    __syncthreads();

    const int tx = t & 15;   // col group
    const int ty = t >> 4;   // row group
    float acc[4][4] = {};
    #pragma unroll
    for (int k = 0; k < 64; k++) {
        float4 av = *(const float4*)&As[k][ty * 4];
        float4 bv = *(const float4*)&Ws[k][tx * 4];
        acc[0][0] += av.x * bv.x; acc[0][1] += av.x * bv.y; acc[0][2] += av.x * bv.z; acc[0][3] += av.x * bv.w;
        acc[1][0] += av.y * bv.x; acc[1][1] += av.y * bv.y; acc[1][2] += av.y * bv.z; acc[1][3] += av.y * bv.w;
        acc[2][0] += av.z * bv.x; acc[2][1] += av.z * bv.y; acc[2][2] += av.z * bv.z; acc[2][3] += av.z * bv.w;
        acc[3][0] += av.w * bv.x; acc[3][1] += av.w * bv.y; acc[3][2] += av.w * bv.z; acc[3][3] += av.w * bv.w;
    }
    #pragma unroll
    for (int i = 0; i < 4; i++) {
        int grow = block_row + ty * 4 + i;
        if (grow < M) {
            float sc = d_dinv[grow];
            __half2 h0 = __floats2half2_rn(acc[i][0] * sc, acc[i][1] * sc);
            __half2 h1 = __floats2half2_rn(acc[i][2] * sc, acc[i][3] * sc);
            uint2 u;
            u.x = *(unsigned int*)&h0;
            u.y = *(unsigned int*)&h1;
            ((uint2*)d_gh)[grow * 16 + tx] = u;
        }
    }
}

__device__ __forceinline__ void acc8(uint4 v, float* a) {
    float2 f0 = __half22float2(*(__half2*)&v.x);
    float2 f1 = __half22float2(*(__half2*)&v.y);
    float2 f2 = __half22float2(*(__half2*)&v.z);
    float2 f3 = __half22float2(*(__half2*)&v.w);
    a[0] += f0.x; a[1] += f0.y; a[2] += f1.x; a[3] += f1.y;
    a[4] += f2.x; a[5] += f2.y; a[6] += f3.x; a[7] += f3.y;
}

// fused aggregation + epilogue: 8 threads per dst node, fp16 gather-reduce,
// out[d] = [relu]( dinv[d] * (sum_{e: dst=d} g[src_e] + g[d]) + b )
// dst_sel: 1 -> write d_h (fp32) with relu ; 0 -> write external out (fp32)
__global__ void k_gat(const float* __restrict__ b, float4* __restrict__ out_ext,
                      int dst_sel) {
    const uint4* __restrict__ g   = d_gh;
    const int*   __restrict__ srt = d_srcSorted;

    int t = blockIdx.x * blockDim.x + threadIdx.x;
    int node = t >> 3;
    if (node >= N_NODES) return;
    int c = t & 7;                          // 8 halves (16B) per thread

    float acc[8] = {};
    acc8(g[node * 8 + c], acc);             // self loop (already dinv-scaled)
    int start = d_rowstart[node];
    int cnt = d_deg[node];

    int j = 0;
    for (; j + 4 <= cnt; j += 4) {          // 4-wide: batch loads for MLP
        int s0 = srt[start + j + 0];
        int s1 = srt[start + j + 1];
        int s2 = srt[start + j + 2];
        int s3 = srt[start + j + 3];
        uint4 v0 = g[s0 * 8 + c];
        uint4 v1 = g[s1 * 8 + c];
        uint4 v2 = g[s2 * 8 + c];
        uint4 v3 = g[s3 * 8 + c];
        acc8(v0, acc); acc8(v1, acc); acc8(v2, acc); acc8(v3, acc);
    }
    for (; j < cnt; j++) {
        int si = srt[start + j];
        acc8(g[si * 8 + c], acc);
    }

    float dv = d_dinv[node];
    float4 b0 = ((const float4*)b)[c * 2 + 0];
    float4 b1 = ((const float4*)b)[c * 2 + 1];
    float4 o0, o1;
    o0.x = fmaf(dv, acc[0], b0.x); o0.y = fmaf(dv, acc[1], b0.y);
    o0.z = fmaf(dv, acc[2], b0.z); o0.w = fmaf(dv, acc[3], b0.w);
    o1.x = fmaf(dv, acc[4], b1.x); o1.y = fmaf(dv, acc[5], b1.y);
    o1.z = fmaf(dv, acc[6], b1.z); o1.w = fmaf(dv, acc[7], b1.w);
    if (dst_sel) {
        o0.x = fmaxf(o0.x, 0.f); o0.y = fmaxf(o0.y, 0.f);
        o0.z = fmaxf(o0.z, 0.f); o0.w = fmaxf(o0.w, 0.f);
        o1.x = fmaxf(o1.x, 0.f); o1.y = fmaxf(o1.y, 0.f);
        o1.z = fmaxf(o1.z, 0.f); o1.w = fmaxf(o1.w, 0.f);
        d_h[node * 16 + c * 2 + 0] = o0;
        d_h[node * 16 + c * 2 + 1] = o1;
    } else {
        out_ext[node * 16 + c * 2 + 0] = o0;
        out_ext[node * 16 + c * 2 + 1] = o1;
    }
}

extern "C" void kernel_launch(void* const* d_in, const int* in_sizes, int n_in,
                              void* d_out, int out_size) {
    const float* x  = (const float*)d_in[0];
    const int*   ei = (const int*)d_in[1];     // int32 view; int64 handled via d_mode
    const float* W1 = (const float*)d_in[2];
    const float* b1 = (const float*)d_in[3];
    const float* W2 = (const float*)d_in[4];
    const float* b2 = (const float*)d_in[5];
    const int E = in_sizes[1] / 2;             // elements of edge_index / 2

    const int TPB = 256;
    const int gridN    = (N_NODES + TPB - 1) / TPB;      // 391
    const int gridE    = (E + TPB - 1) / TPB;
    const int gridGat  = (N_NODES * 8 + TPB - 1) / TPB;  // 3125
    const int gridGemm = (N_NODES + 63) / 64;

    // ---- CSR build (per run) ----
    k_init<<<gridN, TPB>>>(ei);
    k_edge<<<gridE, TPB>>>(ei, E);
    k_scan1<<<NCHUNK, 256>>>();
    k_scan2<<<1, 512>>>();
    k_scan3<<<gridN, TPB>>>();
    k_scatter<<<gridE, TPB>>>(E);

    // ---- layer 1 ----
    k_gemm<<<gridGemm, TPB>>>(x, W1, N_NODES, 0);
    k_gat<<<gridGat, TPB>>>(b1, nullptr, 1);

    // ---- layer 2 ----
    k_gemm<<<gridGemm, TPB>>>(nullptr, W2, N_NODES, 1);
    k_gat<<<gridGat, TPB>>>(b2, (float4*)d_out, 0);
}